// round 16
// baseline (speedup 1.0000x reference)
#include <cuda_runtime.h>
#include <cuda_fp16.h>

#define N_NODES 100000
#define N_EDGES 1250000
#define D 64
#define NB 98          // scan blocks: ceil(N/1024)
#define PAD 18         // smem row stride (floats) for outproj (R8 config)
#define NPB2 1563      // nodehist blocks: ceil(N/64)
#define EPB2 800       // hist edges per nodehist block (1563*800 >= E)

// ---------------- scratch (static __device__ — allocation-free) ----------------
__device__ int     g_cnt[N_NODES];       // zero-init; k_scan re-zeroes after reading
__device__ int     g_scan_state[NB];     // lookback state; k_scatter re-zeroes for next replay
__device__ int     g_rowoff[N_NODES + 1];
__device__ int     g_cursor[N_NODES];
__device__ int     g_sorted_src[N_EDGES];
__device__ __half2 g_packh[N_NODES * D]; // per (node,ch): half2(Q, R), Q=exp(-a_src-u), R=x_lin-u
__device__ float   g_agg[N_NODES * D];   // aggregated messages (pre out-proj)

// ---------------- f32x2 packed helpers (outproj) ----------------
__device__ __forceinline__ unsigned long long pack2(float lo, float hi) {
    unsigned long long r;
    asm("mov.b64 %0, {%1, %2};" : "=l"(r) : "f"(lo), "f"(hi));
    return r;
}
__device__ __forceinline__ void unpack2(unsigned long long v, float& lo, float& hi) {
    asm("mov.b64 {%0, %1}, %2;" : "=f"(lo), "=f"(hi) : "l"(v));
}
__device__ __forceinline__ unsigned long long fma2(unsigned long long a,
                                                   unsigned long long b,
                                                   unsigned long long c) {
    unsigned long long d;
    asm("fma.rn.f32x2 %0, %1, %2, %3;" : "=l"(d) : "l"(a), "l"(b), "l"(c));
    return d;
}

__device__ __forceinline__ unsigned int h2bits(__half2 h) {
    return *reinterpret_cast<unsigned int*>(&h);
}

// ---------------- mma helpers ----------------
__device__ __forceinline__ void ldsmx4(unsigned int* a, const void* p) {
    unsigned int addr = (unsigned int)__cvta_generic_to_shared(p);
    asm volatile("ldmatrix.sync.aligned.m8n8.x4.shared.b16 {%0,%1,%2,%3}, [%4];"
        : "=r"(a[0]), "=r"(a[1]), "=r"(a[2]), "=r"(a[3]) : "r"(addr));
}
__device__ __forceinline__ void ldsmx2t(unsigned int* b, const void* p) {
    unsigned int addr = (unsigned int)__cvta_generic_to_shared(p);
    asm volatile("ldmatrix.sync.aligned.m8n8.x2.trans.shared.b16 {%0,%1}, [%2];"
        : "=r"(b[0]), "=r"(b[1]) : "r"(addr));
}
__device__ __forceinline__ void mma16816(float* d, const unsigned int* a, const unsigned int* b) {
    asm volatile("mma.sync.aligned.m16n8k16.row.col.f32.f16.f16.f32 "
        "{%0,%1,%2,%3}, {%4,%5,%6,%7}, {%8,%9}, {%0,%1,%2,%3};"
        : "+f"(d[0]), "+f"(d[1]), "+f"(d[2]), "+f"(d[3])
        : "r"(a[0]), "r"(a[1]), "r"(a[2]), "r"(a[3]), "r"(b[0]), "r"(b[1]));
}

// int64-vs-int32 edge dtype probe (first 16 entries)
__device__ __forceinline__ int detect_is64(const void* eiv) {
    const long long* p = (const long long*)eiv;
    int is64 = 1;
#pragma unroll
    for (int j = 0; j < 16; j++) {
        long long v = p[j];
        if (v < 0 || v >= (long long)N_NODES) is64 = 0;
    }
    return is64;
}

__device__ __forceinline__ int load_idx(const void* eiv, int pos64, int is64) {
    if (is64) return (int)((const long long*)eiv)[pos64];
    return ((const int*)eiv)[pos64];
}

// stage a 64x64 f32 row-major matrix into half smem [64][72] — coalesced:
// each warp owns 16 rows; lane l loads float2 at col 2l (contiguous 256B per instr).
__device__ __forceinline__ void stage_w(const float* __restrict__ src, __half (*dst)[72],
                                        int w, int lane) {
#pragma unroll
    for (int i = 0; i < 16; i++) {
        int r = w * 16 + i;
        float2 v = *(const float2*)(src + r * 64 + 2 * lane);
        *(__half2*)&dst[r][2 * lane] = __float22half2_rn(v);
    }
}

// ---------------- fused: tensor-core node projections + hist slice ----------------
// 64 nodes / 128-thread block (4 warps x 16 rows). fp16 mma, fp32 accumulate.
// Epilogue stores bounce through smem so g_packh stores are row-coalesced (nL=1).
__global__ void __launch_bounds__(128) k_nodehist(
        const void* __restrict__ eiv,
        const float* __restrict__ x, const float* __restrict__ pos,
        const float* __restrict__ W_in, const float* __restrict__ b_in,
        const float* __restrict__ W_lin, const float* __restrict__ W_src,
        const float* __restrict__ W_pos) {
    __shared__ __align__(16) __half xh[64][72];
    __shared__ __align__(16) __half wsh[2][64][72];
    __shared__ unsigned int sstage[64][33];   // one N-half of pack values (uint = half2(Q,R))
    __shared__ float spos[192];
    __shared__ int sflag;

    int t = threadIdx.x;
    int w = t >> 5;
    int lane = t & 31;
    int n0 = blockIdx.x * 64;

    // ---- stage x (fp32 -> fp16, coalesced), W_in, pos, dtype flag ----
#pragma unroll
    for (int i = 0; i < 16; i++) {
        int r = w * 16 + i;
        int node = n0 + r;
        float2 v = (node < N_NODES) ? *(const float2*)(x + (size_t)node * 64 + 2 * lane)
                                    : make_float2(0.f, 0.f);
        *(__half2*)&xh[r][2 * lane] = __float22half2_rn(v);
    }
    stage_w(W_in, wsh[0], w, lane);
    for (int i = t; i < 192; i += 128) {
        int idx = n0 * 3 + i;
        spos[i] = (idx < 3 * N_NODES) ? pos[idx] : 0.f;
    }
    if (t == 0) sflag = detect_is64(eiv);
    __syncthreads();

    // ---- hist slice (fire-and-forget atomics, overlap GEMMs) ----
    {
        int is64 = sflag;
        int base = blockIdx.x * EPB2;
        for (int e = base + t; e < base + EPB2; e += 128) {
            if (e < N_EDGES) {
                int d = load_idx(eiv, N_EDGES + e, is64);
                if ((unsigned)d < (unsigned)N_NODES) atomicAdd(&g_cnt[d], 1);
            }
        }
    }

    // fragment addressing
    int g = lane >> 3;
    int arow = 16 * w + (g & 1) * 8 + (lane & 7);
    int acol0 = (g >> 1) * 8;
    int brow = lane & 15;
    int r0 = 16 * w + (lane >> 2);
    int cb = 2 * (lane & 3);

    unsigned int aF[4], bF[2];

    // ---- GEMM 1: h = relu(x @ W_in + b_in) ----
    float acc[8][4];
#pragma unroll
    for (int nt = 0; nt < 8; nt++)
#pragma unroll
        for (int i = 0; i < 4; i++) acc[nt][i] = 0.f;
#pragma unroll
    for (int kt = 0; kt < 4; kt++) {
        ldsmx4(aF, &xh[arow][kt * 16 + acol0]);
#pragma unroll
        for (int nt = 0; nt < 8; nt++) {
            ldsmx2t(bF, &wsh[0][kt * 16 + brow][nt * 8]);
            mma16816(acc[nt], aF, bF);
        }
    }
    // h -> xh (own warp's rows only; safe without block sync)
#pragma unroll
    for (int nt = 0; nt < 8; nt++) {
        float2 bb = *(const float2*)&b_in[nt * 8 + cb];
        __half2 h01 = __floats2half2_rn(fmaxf(acc[nt][0] + bb.x, 0.f),
                                        fmaxf(acc[nt][1] + bb.y, 0.f));
        __half2 h23 = __floats2half2_rn(fmaxf(acc[nt][2] + bb.x, 0.f),
                                        fmaxf(acc[nt][3] + bb.y, 0.f));
        *(__half2*)&xh[r0][nt * 8 + cb] = h01;
        *(__half2*)&xh[r0 + 8][nt * 8 + cb] = h23;
    }
    __syncthreads();
    stage_w(W_lin, wsh[0], w, lane);
    stage_w(W_src, wsh[1], w, lane);
    __syncthreads();

    // ---- GEMMs 2+3 (x_lin, a_src) in two N-halves + staged epilogue ----
#pragma unroll
    for (int hv = 0; hv < 2; hv++) {
        float aL[4][4], aS[4][4];
#pragma unroll
        for (int nt = 0; nt < 4; nt++)
#pragma unroll
            for (int i = 0; i < 4; i++) { aL[nt][i] = 0.f; aS[nt][i] = 0.f; }
#pragma unroll
        for (int kt = 0; kt < 4; kt++) {
            ldsmx4(aF, &xh[arow][kt * 16 + acol0]);
#pragma unroll
            for (int nt = 0; nt < 4; nt++) {
                int ncol = (hv * 4 + nt) * 8;
                ldsmx2t(bF, &wsh[0][kt * 16 + brow][ncol]);
                mma16816(aL[nt], aF, bF);
                ldsmx2t(bF, &wsh[1][kt * 16 + brow][ncol]);
                mma16816(aS[nt], aF, bF);
            }
        }
        // epilogue: u = pos@W_pos; Q = exp(-a_src-u); R = x_lin-u -> smem
#pragma unroll
        for (int nt = 0; nt < 4; nt++) {
            int col = (hv * 4 + nt) * 8 + cb;   // global channel
            int cl = nt * 8 + cb;               // local (within N-half)
            float2 w0 = *(const float2*)&W_pos[0 * 64 + col];
            float2 w1 = *(const float2*)&W_pos[1 * 64 + col];
            float2 w2 = *(const float2*)&W_pos[2 * 64 + col];
#pragma unroll
            for (int rr = 0; rr < 2; rr++) {
                int li = r0 + rr * 8;
                float p0 = spos[li * 3], p1 = spos[li * 3 + 1], p2 = spos[li * 3 + 2];
                float u0 = fmaf(p2, w2.x, fmaf(p1, w1.x, p0 * w0.x));
                float u1 = fmaf(p2, w2.y, fmaf(p1, w1.y, p0 * w0.y));
                float q0 = __expf(-aS[nt][rr * 2 + 0] - u0);
                float R0 = aL[nt][rr * 2 + 0] - u0;
                float q1 = __expf(-aS[nt][rr * 2 + 1] - u1);
                float R1 = aL[nt][rr * 2 + 1] - u1;
                sstage[li][cl]     = h2bits(__floats2half2_rn(q0, R0));
                sstage[li][cl + 1] = h2bits(__floats2half2_rn(q1, R1));
            }
        }
        __syncthreads();
        // coalesced flush: warp stores contiguous 128B row-halves (nL=1)
        unsigned int* gp = (unsigned int*)g_packh;
#pragma unroll
        for (int i = 0; i < 16; i++) {
            int r = w * 16 + i;
            int node = n0 + r;
            if (node < N_NODES) gp[node * 64 + hv * 32 + lane] = sstage[r][lane];
        }
        __syncthreads();
    }
}

// ---------------- single-pass scan with decoupled lookback ----------------
__global__ void k_scan_lookback() {
    __shared__ int warpsum[32];
    __shared__ int s_prefix;
    int t = threadIdx.x;
    int b = blockIdx.x;
    int i = b * 1024 + t;
    int v = (i < N_NODES) ? g_cnt[i] : 0;
    if (i < N_NODES) g_cnt[i] = 0;

    int x = v;
#pragma unroll
    for (int o = 1; o < 32; o <<= 1) {
        int y = __shfl_up_sync(0xffffffffu, x, o);
        if ((t & 31) >= o) x += y;
    }
    if ((t & 31) == 31) warpsum[t >> 5] = x;
    __syncthreads();
    if (t < 32) {
        int w = warpsum[t];
#pragma unroll
        for (int o = 1; o < 32; o <<= 1) {
            int y = __shfl_up_sync(0xffffffffu, w, o);
            if (t >= o) w += y;
        }
        warpsum[t] = w;
    }
    __syncthreads();
    int wid = t >> 5;
    int incl = x + (wid ? warpsum[wid - 1] : 0);
    int block_agg = warpsum[31];

    if (t == 0) {
        if (b == 0) {
            atomicExch(&g_scan_state[0], (block_agg << 2) | 2);
            s_prefix = 0;
        } else {
            atomicExch(&g_scan_state[b], (block_agg << 2) | 1);
            int sum = 0;
            int j = b - 1;
            while (j >= 0) {
                int s = atomicAdd(&g_scan_state[j], 0);
                int st = s & 3;
                if (st == 0) continue;
                sum += (s >> 2);
                if (st == 2) break;
                j--;
            }
            s_prefix = sum;
            atomicExch(&g_scan_state[b], ((sum + block_agg) << 2) | 2);
        }
    }
    __syncthreads();
    int pre = s_prefix;

    int off = pre + incl - v;
    if (i < N_NODES) {
        g_rowoff[i] = off;
        g_cursor[i] = off;
    }
    if (i == N_NODES - 1) g_rowoff[N_NODES] = pre + incl;
}

// ---------------- scatter: 2 edges/thread, vectorized edge-list loads ----------------
__global__ void k_scatter(const void* __restrict__ eiv) {
    __shared__ int sflag;
    if (threadIdx.x == 0) sflag = detect_is64(eiv);
    __syncthreads();
    int is64 = sflag;

    if (blockIdx.x == 0 && threadIdx.x < NB) g_scan_state[threadIdx.x] = 0;

    int e2 = blockIdx.x * blockDim.x + threadIdx.x;   // edge-pair index
    int e = 2 * e2;
    if (e < N_EDGES) {
        int s0, s1, d0, d1;
        if (is64) {
            longlong2 sp = *((const longlong2*)eiv + e2);
            longlong2 dp = *(const longlong2*)((const long long*)eiv + N_EDGES + e);
            s0 = (int)sp.x; s1 = (int)sp.y;
            d0 = (int)dp.x; d1 = (int)dp.y;
        } else {
            int2 sp = *((const int2*)eiv + e2);
            int2 dp = *(const int2*)((const int*)eiv + N_EDGES + e);
            s0 = sp.x; s1 = sp.y;
            d0 = dp.x; d1 = dp.y;
        }
        if ((unsigned)d0 < (unsigned)N_NODES) {
            int p = atomicAdd(&g_cursor[d0], 1);
            g_sorted_src[p] = ((unsigned)s0 < (unsigned)N_NODES) ? s0 : 0;
        }
        if (e + 1 < N_EDGES && (unsigned)d1 < (unsigned)N_NODES) {
            int p = atomicAdd(&g_cursor[d1], 1);
            g_sorted_src[p] = ((unsigned)s1 < (unsigned)N_NODES) ? s1 : 0;
        }
    }
}

// ---------------- edge pass (R8-exact): agg = (Σ Q·R)/(Σ Q) + (u[dst]+b_pos) ----------------
__global__ void k_edge(const float* __restrict__ pos,
                       const float* __restrict__ W_pos, const float* __restrict__ b_pos) {
    int warp = threadIdx.x >> 5;
    int lane = threadIdx.x & 31;
    int dst = blockIdx.x * 8 + warp;

    int rs = g_rowoff[dst];
    int re = g_rowoff[dst + 1];

    float sq0 = 0.f, sr0 = 0.f, sq1 = 0.f, sr1 = 0.f;

    for (int base = rs; base < re; base += 32) {
        int m = min(32, re - base);
        int idx = (lane < m) ? g_sorted_src[base + lane] : 0;
        int j = 0;
        for (; j + 4 <= m; j += 4) {
            int s0 = __shfl_sync(0xffffffffu, idx, j);
            int s1 = __shfl_sync(0xffffffffu, idx, j + 1);
            int s2 = __shfl_sync(0xffffffffu, idx, j + 2);
            int s3 = __shfl_sync(0xffffffffu, idx, j + 3);
            uint2 v0 = *reinterpret_cast<const uint2*>(&g_packh[s0 * D + 2 * lane]);
            uint2 v1 = *reinterpret_cast<const uint2*>(&g_packh[s1 * D + 2 * lane]);
            uint2 v2 = *reinterpret_cast<const uint2*>(&g_packh[s2 * D + 2 * lane]);
            uint2 v3 = *reinterpret_cast<const uint2*>(&g_packh[s3 * D + 2 * lane]);
            float2 a0 = __half22float2(*reinterpret_cast<const __half2*>(&v0.x));
            float2 b0 = __half22float2(*reinterpret_cast<const __half2*>(&v0.y));
            float2 a1 = __half22float2(*reinterpret_cast<const __half2*>(&v1.x));
            float2 b1 = __half22float2(*reinterpret_cast<const __half2*>(&v1.y));
            float2 a2 = __half22float2(*reinterpret_cast<const __half2*>(&v2.x));
            float2 b2 = __half22float2(*reinterpret_cast<const __half2*>(&v2.y));
            float2 a3 = __half22float2(*reinterpret_cast<const __half2*>(&v3.x));
            float2 b3 = __half22float2(*reinterpret_cast<const __half2*>(&v3.y));
            sq0 += a0.x; sr0 = fmaf(a0.x, a0.y, sr0);
            sq1 += b0.x; sr1 = fmaf(b0.x, b0.y, sr1);
            sq0 += a1.x; sr0 = fmaf(a1.x, a1.y, sr0);
            sq1 += b1.x; sr1 = fmaf(b1.x, b1.y, sr1);
            sq0 += a2.x; sr0 = fmaf(a2.x, a2.y, sr0);
            sq1 += b2.x; sr1 = fmaf(b2.x, b2.y, sr1);
            sq0 += a3.x; sr0 = fmaf(a3.x, a3.y, sr0);
            sq1 += b3.x; sr1 = fmaf(b3.x, b3.y, sr1);
        }
        for (; j < m; j++) {
            int s0 = __shfl_sync(0xffffffffu, idx, j);
            uint2 v0 = *reinterpret_cast<const uint2*>(&g_packh[s0 * D + 2 * lane]);
            float2 a0 = __half22float2(*reinterpret_cast<const __half2*>(&v0.x));
            float2 b0 = __half22float2(*reinterpret_cast<const __half2*>(&v0.y));
            sq0 += a0.x; sr0 = fmaf(a0.x, a0.y, sr0);
            sq1 += b0.x; sr1 = fmaf(b0.x, b0.y, sr1);
        }
    }

    int c0 = 2 * lane;
    if (re > rs) {
        float p0 = pos[dst * 3 + 0], p1 = pos[dst * 3 + 1], p2 = pos[dst * 3 + 2];
        float u0 = fmaf(p2, W_pos[2 * D + c0],     fmaf(p1, W_pos[1 * D + c0],     p0 * W_pos[0 * D + c0]));
        float u1 = fmaf(p2, W_pos[2 * D + c0 + 1], fmaf(p1, W_pos[1 * D + c0 + 1], p0 * W_pos[0 * D + c0 + 1]));
        g_agg[dst * D + c0]     = sr0 / sq0 + u0 + b_pos[c0];
        g_agg[dst * D + c0 + 1] = sr1 / sq1 + u1 + b_pos[c0 + 1];
    } else {
        g_agg[dst * D + c0]     = 0.0f;
        g_agg[dst * D + c0 + 1] = 0.0f;
    }
}

// ---------------- out projection (R8-exact): out = relu(agg @ W_out + b_out) ----------------
__global__ void k_outproj(const float* __restrict__ W_out, const float* __restrict__ b_out,
                          float* __restrict__ out) {
    __shared__ float sh[D][PAD];
    int c = threadIdx.x;
    int n0 = blockIdx.x * 16;

#pragma unroll
    for (int r = 0; r < 16; r++) sh[c][r] = g_agg[(n0 + r) * D + c];
    __syncthreads();

    float bo = b_out[c];
    unsigned long long op[8];
#pragma unroll
    for (int p = 0; p < 8; p++) op[p] = pack2(bo, bo);
#pragma unroll 4
    for (int k = 0; k < D; k++) {
        float w = W_out[k * D + c];
        unsigned long long ww = pack2(w, w);
#pragma unroll
        for (int p = 0; p < 8; p++) {
            unsigned long long ap = *(const unsigned long long*)&sh[k][2 * p];
            op[p] = fma2(ap, ww, op[p]);
        }
    }
#pragma unroll
    for (int p = 0; p < 8; p++) {
        float o0, o1;
        unpack2(op[p], o0, o1);
        out[(n0 + 2 * p) * D + c]     = fmaxf(o0, 0.0f);
        out[(n0 + 2 * p + 1) * D + c] = fmaxf(o1, 0.0f);
    }
}

// ---------------- launch ----------------
extern "C" void kernel_launch(void* const* d_in, const int* in_sizes, int n_in,
                              void* d_out, int out_size) {
    const float* x     = (const float*)d_in[0];
    const float* pos   = (const float*)d_in[1];
    const void*  ei    = d_in[2];
    const float* W_in  = (const float*)d_in[3];
    const float* b_in  = (const float*)d_in[4];
    const float* W_lin = (const float*)d_in[5];
    const float* W_src = (const float*)d_in[6];
    // d_in[7] = W_dst: dead (dst-side softmax terms cancel)
    const float* W_pos = (const float*)d_in[8];
    const float* b_pos = (const float*)d_in[9];
    const float* W_out = (const float*)d_in[10];
    const float* b_out = (const float*)d_in[11];
    float* out = (float*)d_out;

    k_nodehist<<<NPB2, 128>>>(ei, x, pos, W_in, b_in, W_lin, W_src, W_pos);
    k_scan_lookback<<<NB, 1024>>>();
    k_scatter<<<(N_EDGES / 2 + 255) / 256, 256>>>(ei);
    k_edge<<<N_NODES / 8, 256>>>(pos, W_pos, b_pos);   // captured slot #4
    k_outproj<<<N_NODES / 16, 64>>>(W_out, b_out, out);
}

// round 17
// speedup vs baseline: 1.0387x; 1.0387x over previous
#include <cuda_runtime.h>
#include <cuda_fp16.h>

#define N_NODES 100000
#define N_EDGES 1250000
#define D 64
#define NB 98          // scan blocks: ceil(N/1024)
#define PAD 18         // smem row stride (floats) for outproj (R8 config)
#define NPB2 1563      // nodehist blocks: ceil(N/64)
#define EPB2 800       // hist edges per nodehist block (1563*800 >= E)

// ---------------- scratch (static __device__ — allocation-free) ----------------
__device__ int     g_cnt[N_NODES];       // zero-init; k_scan re-zeroes after reading
__device__ int     g_scan_state[NB];     // lookback state; k_scatter re-zeroes for next replay
__device__ int     g_rowoff[N_NODES + 1];
__device__ int     g_cursor[N_NODES];
__device__ int     g_sorted_src[N_EDGES];
__device__ __half2 g_packh[N_NODES * D]; // per (node,ch): half2(Q, R), Q=exp(-a_src-u), R=x_lin-u
__device__ float   g_agg[N_NODES * D];   // aggregated messages (pre out-proj)

// ---------------- f32x2 packed helpers (outproj) ----------------
__device__ __forceinline__ unsigned long long pack2(float lo, float hi) {
    unsigned long long r;
    asm("mov.b64 %0, {%1, %2};" : "=l"(r) : "f"(lo), "f"(hi));
    return r;
}
__device__ __forceinline__ void unpack2(unsigned long long v, float& lo, float& hi) {
    asm("mov.b64 {%0, %1}, %2;" : "=f"(lo), "=f"(hi) : "l"(v));
}
__device__ __forceinline__ unsigned long long fma2(unsigned long long a,
                                                   unsigned long long b,
                                                   unsigned long long c) {
    unsigned long long d;
    asm("fma.rn.f32x2 %0, %1, %2, %3;" : "=l"(d) : "l"(a), "l"(b), "l"(c));
    return d;
}

__device__ __forceinline__ unsigned int h2bits(__half2 h) {
    return *reinterpret_cast<unsigned int*>(&h);
}

// ---------------- mma helpers ----------------
__device__ __forceinline__ void ldsmx4(unsigned int* a, const void* p) {
    unsigned int addr = (unsigned int)__cvta_generic_to_shared(p);
    asm volatile("ldmatrix.sync.aligned.m8n8.x4.shared.b16 {%0,%1,%2,%3}, [%4];"
        : "=r"(a[0]), "=r"(a[1]), "=r"(a[2]), "=r"(a[3]) : "r"(addr));
}
__device__ __forceinline__ void ldsmx2t(unsigned int* b, const void* p) {
    unsigned int addr = (unsigned int)__cvta_generic_to_shared(p);
    asm volatile("ldmatrix.sync.aligned.m8n8.x2.trans.shared.b16 {%0,%1}, [%2];"
        : "=r"(b[0]), "=r"(b[1]) : "r"(addr));
}
__device__ __forceinline__ void mma16816(float* d, const unsigned int* a, const unsigned int* b) {
    asm volatile("mma.sync.aligned.m16n8k16.row.col.f32.f16.f16.f32 "
        "{%0,%1,%2,%3}, {%4,%5,%6,%7}, {%8,%9}, {%0,%1,%2,%3};"
        : "+f"(d[0]), "+f"(d[1]), "+f"(d[2]), "+f"(d[3])
        : "r"(a[0]), "r"(a[1]), "r"(a[2]), "r"(a[3]), "r"(b[0]), "r"(b[1]));
}

// int64-vs-int32 edge dtype probe (first 16 entries)
__device__ __forceinline__ int detect_is64(const void* eiv) {
    const long long* p = (const long long*)eiv;
    int is64 = 1;
#pragma unroll
    for (int j = 0; j < 16; j++) {
        long long v = p[j];
        if (v < 0 || v >= (long long)N_NODES) is64 = 0;
    }
    return is64;
}

__device__ __forceinline__ int load_idx(const void* eiv, int pos64, int is64) {
    if (is64) return (int)((const long long*)eiv)[pos64];
    return ((const int*)eiv)[pos64];
}

// stage a 64x64 f32 row-major matrix into half smem [64][72] — coalesced:
// each warp owns 16 rows; lane l loads float2 at col 2l (contiguous 256B per instr).
__device__ __forceinline__ void stage_w(const float* __restrict__ src, __half (*dst)[72],
                                        int w, int lane) {
#pragma unroll
    for (int i = 0; i < 16; i++) {
        int r = w * 16 + i;
        float2 v = *(const float2*)(src + r * 64 + 2 * lane);
        *(__half2*)&dst[r][2 * lane] = __float22half2_rn(v);
    }
}

// ---------------- fused: tensor-core node projections + hist slice (R15-exact) ----------------
// 64 nodes / 128-thread block (4 warps x 16 rows). fp16 mma, fp32 accumulate.
__global__ void __launch_bounds__(128) k_nodehist(
        const void* __restrict__ eiv,
        const float* __restrict__ x, const float* __restrict__ pos,
        const float* __restrict__ W_in, const float* __restrict__ b_in,
        const float* __restrict__ W_lin, const float* __restrict__ W_src,
        const float* __restrict__ W_pos) {
    __shared__ __align__(16) __half xh[64][72];
    __shared__ __align__(16) __half wsh[2][64][72];
    __shared__ float spos[192];
    __shared__ int sflag;

    int t = threadIdx.x;
    int w = t >> 5;
    int lane = t & 31;
    int n0 = blockIdx.x * 64;

    // ---- stage x (fp32 -> fp16, coalesced), W_in, pos, dtype flag ----
#pragma unroll
    for (int i = 0; i < 16; i++) {
        int r = w * 16 + i;
        int node = n0 + r;
        float2 v = (node < N_NODES) ? *(const float2*)(x + (size_t)node * 64 + 2 * lane)
                                    : make_float2(0.f, 0.f);
        *(__half2*)&xh[r][2 * lane] = __float22half2_rn(v);
    }
    stage_w(W_in, wsh[0], w, lane);
    for (int i = t; i < 192; i += 128) {
        int idx = n0 * 3 + i;
        spos[i] = (idx < 3 * N_NODES) ? pos[idx] : 0.f;
    }
    if (t == 0) sflag = detect_is64(eiv);
    __syncthreads();

    // ---- hist slice (fire-and-forget atomics, overlap GEMMs) ----
    {
        int is64 = sflag;
        int base = blockIdx.x * EPB2;
        for (int e = base + t; e < base + EPB2; e += 128) {
            if (e < N_EDGES) {
                int d = load_idx(eiv, N_EDGES + e, is64);
                if ((unsigned)d < (unsigned)N_NODES) atomicAdd(&g_cnt[d], 1);
            }
        }
    }

    // fragment addressing
    int g = lane >> 3;
    int arow = 16 * w + (g & 1) * 8 + (lane & 7);
    int acol0 = (g >> 1) * 8;
    int brow = lane & 15;
    int r0 = 16 * w + (lane >> 2);
    int cb = 2 * (lane & 3);

    unsigned int aF[4], bF[2];

    // ---- GEMM 1: h = relu(x @ W_in + b_in) ----
    float acc[8][4];
#pragma unroll
    for (int nt = 0; nt < 8; nt++)
#pragma unroll
        for (int i = 0; i < 4; i++) acc[nt][i] = 0.f;
#pragma unroll
    for (int kt = 0; kt < 4; kt++) {
        ldsmx4(aF, &xh[arow][kt * 16 + acol0]);
#pragma unroll
        for (int nt = 0; nt < 8; nt++) {
            ldsmx2t(bF, &wsh[0][kt * 16 + brow][nt * 8]);
            mma16816(acc[nt], aF, bF);
        }
    }
    // h -> xh (own warp's rows only; safe without block sync)
#pragma unroll
    for (int nt = 0; nt < 8; nt++) {
        float2 bb = *(const float2*)&b_in[nt * 8 + cb];
        __half2 h01 = __floats2half2_rn(fmaxf(acc[nt][0] + bb.x, 0.f),
                                        fmaxf(acc[nt][1] + bb.y, 0.f));
        __half2 h23 = __floats2half2_rn(fmaxf(acc[nt][2] + bb.x, 0.f),
                                        fmaxf(acc[nt][3] + bb.y, 0.f));
        *(__half2*)&xh[r0][nt * 8 + cb] = h01;
        *(__half2*)&xh[r0 + 8][nt * 8 + cb] = h23;
    }
    __syncthreads();
    stage_w(W_lin, wsh[0], w, lane);
    stage_w(W_src, wsh[1], w, lane);
    __syncthreads();

    // ---- GEMMs 2+3 (x_lin, a_src) in two N-halves + fused epilogue ----
#pragma unroll
    for (int hv = 0; hv < 2; hv++) {
        float aL[4][4], aS[4][4];
#pragma unroll
        for (int nt = 0; nt < 4; nt++)
#pragma unroll
            for (int i = 0; i < 4; i++) { aL[nt][i] = 0.f; aS[nt][i] = 0.f; }
#pragma unroll
        for (int kt = 0; kt < 4; kt++) {
            ldsmx4(aF, &xh[arow][kt * 16 + acol0]);
#pragma unroll
            for (int nt = 0; nt < 4; nt++) {
                int ncol = (hv * 4 + nt) * 8;
                ldsmx2t(bF, &wsh[0][kt * 16 + brow][ncol]);
                mma16816(aL[nt], aF, bF);
                ldsmx2t(bF, &wsh[1][kt * 16 + brow][ncol]);
                mma16816(aS[nt], aF, bF);
            }
        }
        // epilogue: u = pos@W_pos; Q = exp(-a_src-u); R = x_lin-u (direct stores)
#pragma unroll
        for (int nt = 0; nt < 4; nt++) {
            int col = (hv * 4 + nt) * 8 + cb;
            float2 w0 = *(const float2*)&W_pos[0 * 64 + col];
            float2 w1 = *(const float2*)&W_pos[1 * 64 + col];
            float2 w2 = *(const float2*)&W_pos[2 * 64 + col];
#pragma unroll
            for (int rr = 0; rr < 2; rr++) {
                int li = r0 + rr * 8;
                int node = n0 + li;
                if (node < N_NODES) {
                    float p0 = spos[li * 3], p1 = spos[li * 3 + 1], p2 = spos[li * 3 + 2];
                    float u0 = fmaf(p2, w2.x, fmaf(p1, w1.x, p0 * w0.x));
                    float u1 = fmaf(p2, w2.y, fmaf(p1, w1.y, p0 * w0.y));
                    float q0 = __expf(-aS[nt][rr * 2 + 0] - u0);
                    float R0 = aL[nt][rr * 2 + 0] - u0;
                    float q1 = __expf(-aS[nt][rr * 2 + 1] - u1);
                    float R1 = aL[nt][rr * 2 + 1] - u1;
                    uint2 st;
                    st.x = h2bits(__floats2half2_rn(q0, R0));
                    st.y = h2bits(__floats2half2_rn(q1, R1));
                    *(uint2*)&g_packh[node * D + col] = st;
                }
            }
        }
    }
}

// ---------------- single-pass scan with decoupled lookback ----------------
__global__ void k_scan_lookback() {
    __shared__ int warpsum[32];
    __shared__ int s_prefix;
    int t = threadIdx.x;
    int b = blockIdx.x;
    int i = b * 1024 + t;
    int v = (i < N_NODES) ? g_cnt[i] : 0;
    if (i < N_NODES) g_cnt[i] = 0;

    int x = v;
#pragma unroll
    for (int o = 1; o < 32; o <<= 1) {
        int y = __shfl_up_sync(0xffffffffu, x, o);
        if ((t & 31) >= o) x += y;
    }
    if ((t & 31) == 31) warpsum[t >> 5] = x;
    __syncthreads();
    if (t < 32) {
        int w = warpsum[t];
#pragma unroll
        for (int o = 1; o < 32; o <<= 1) {
            int y = __shfl_up_sync(0xffffffffu, w, o);
            if (t >= o) w += y;
        }
        warpsum[t] = w;
    }
    __syncthreads();
    int wid = t >> 5;
    int incl = x + (wid ? warpsum[wid - 1] : 0);
    int block_agg = warpsum[31];

    if (t == 0) {
        if (b == 0) {
            atomicExch(&g_scan_state[0], (block_agg << 2) | 2);
            s_prefix = 0;
        } else {
            atomicExch(&g_scan_state[b], (block_agg << 2) | 1);
            int sum = 0;
            int j = b - 1;
            while (j >= 0) {
                int s = atomicAdd(&g_scan_state[j], 0);
                int st = s & 3;
                if (st == 0) continue;
                sum += (s >> 2);
                if (st == 2) break;
                j--;
            }
            s_prefix = sum;
            atomicExch(&g_scan_state[b], ((sum + block_agg) << 2) | 2);
        }
    }
    __syncthreads();
    int pre = s_prefix;

    int off = pre + incl - v;
    if (i < N_NODES) {
        g_rowoff[i] = off;
        g_cursor[i] = off;
    }
    if (i == N_NODES - 1) g_rowoff[N_NODES] = pre + incl;
}

// ---------------- scatter: 2 edges/thread, vectorized edge-list loads ----------------
__global__ void k_scatter(const void* __restrict__ eiv) {
    __shared__ int sflag;
    if (threadIdx.x == 0) sflag = detect_is64(eiv);
    __syncthreads();
    int is64 = sflag;

    if (blockIdx.x == 0 && threadIdx.x < NB) g_scan_state[threadIdx.x] = 0;

    int e2 = blockIdx.x * blockDim.x + threadIdx.x;   // edge-pair index
    int e = 2 * e2;
    if (e < N_EDGES) {
        int s0, s1, d0, d1;
        if (is64) {
            longlong2 sp = *((const longlong2*)eiv + e2);
            longlong2 dp = *(const longlong2*)((const long long*)eiv + N_EDGES + e);
            s0 = (int)sp.x; s1 = (int)sp.y;
            d0 = (int)dp.x; d1 = (int)dp.y;
        } else {
            int2 sp = *((const int2*)eiv + e2);
            int2 dp = *(const int2*)((const int*)eiv + N_EDGES + e);
            s0 = sp.x; s1 = sp.y;
            d0 = dp.x; d1 = dp.y;
        }
        if ((unsigned)d0 < (unsigned)N_NODES) {
            int p = atomicAdd(&g_cursor[d0], 1);
            g_sorted_src[p] = ((unsigned)s0 < (unsigned)N_NODES) ? s0 : 0;
        }
        if (e + 1 < N_EDGES && (unsigned)d1 < (unsigned)N_NODES) {
            int p = atomicAdd(&g_cursor[d1], 1);
            g_sorted_src[p] = ((unsigned)s1 < (unsigned)N_NODES) ? s1 : 0;
        }
    }
}

// ---------------- edge pass (R8-exact): agg = (Σ Q·R)/(Σ Q) + (u[dst]+b_pos) ----------------
__global__ void k_edge(const float* __restrict__ pos,
                       const float* __restrict__ W_pos, const float* __restrict__ b_pos) {
    int warp = threadIdx.x >> 5;
    int lane = threadIdx.x & 31;
    int dst = blockIdx.x * 8 + warp;

    int rs = g_rowoff[dst];
    int re = g_rowoff[dst + 1];

    float sq0 = 0.f, sr0 = 0.f, sq1 = 0.f, sr1 = 0.f;

    for (int base = rs; base < re; base += 32) {
        int m = min(32, re - base);
        int idx = (lane < m) ? g_sorted_src[base + lane] : 0;
        int j = 0;
        for (; j + 4 <= m; j += 4) {
            int s0 = __shfl_sync(0xffffffffu, idx, j);
            int s1 = __shfl_sync(0xffffffffu, idx, j + 1);
            int s2 = __shfl_sync(0xffffffffu, idx, j + 2);
            int s3 = __shfl_sync(0xffffffffu, idx, j + 3);
            uint2 v0 = *reinterpret_cast<const uint2*>(&g_packh[s0 * D + 2 * lane]);
            uint2 v1 = *reinterpret_cast<const uint2*>(&g_packh[s1 * D + 2 * lane]);
            uint2 v2 = *reinterpret_cast<const uint2*>(&g_packh[s2 * D + 2 * lane]);
            uint2 v3 = *reinterpret_cast<const uint2*>(&g_packh[s3 * D + 2 * lane]);
            float2 a0 = __half22float2(*reinterpret_cast<const __half2*>(&v0.x));
            float2 b0 = __half22float2(*reinterpret_cast<const __half2*>(&v0.y));
            float2 a1 = __half22float2(*reinterpret_cast<const __half2*>(&v1.x));
            float2 b1 = __half22float2(*reinterpret_cast<const __half2*>(&v1.y));
            float2 a2 = __half22float2(*reinterpret_cast<const __half2*>(&v2.x));
            float2 b2 = __half22float2(*reinterpret_cast<const __half2*>(&v2.y));
            float2 a3 = __half22float2(*reinterpret_cast<const __half2*>(&v3.x));
            float2 b3 = __half22float2(*reinterpret_cast<const __half2*>(&v3.y));
            sq0 += a0.x; sr0 = fmaf(a0.x, a0.y, sr0);
            sq1 += b0.x; sr1 = fmaf(b0.x, b0.y, sr1);
            sq0 += a1.x; sr0 = fmaf(a1.x, a1.y, sr0);
            sq1 += b1.x; sr1 = fmaf(b1.x, b1.y, sr1);
            sq0 += a2.x; sr0 = fmaf(a2.x, a2.y, sr0);
            sq1 += b2.x; sr1 = fmaf(b2.x, b2.y, sr1);
            sq0 += a3.x; sr0 = fmaf(a3.x, a3.y, sr0);
            sq1 += b3.x; sr1 = fmaf(b3.x, b3.y, sr1);
        }
        for (; j < m; j++) {
            int s0 = __shfl_sync(0xffffffffu, idx, j);
            uint2 v0 = *reinterpret_cast<const uint2*>(&g_packh[s0 * D + 2 * lane]);
            float2 a0 = __half22float2(*reinterpret_cast<const __half2*>(&v0.x));
            float2 b0 = __half22float2(*reinterpret_cast<const __half2*>(&v0.y));
            sq0 += a0.x; sr0 = fmaf(a0.x, a0.y, sr0);
            sq1 += b0.x; sr1 = fmaf(b0.x, b0.y, sr1);
        }
    }

    int c0 = 2 * lane;
    if (re > rs) {
        float p0 = pos[dst * 3 + 0], p1 = pos[dst * 3 + 1], p2 = pos[dst * 3 + 2];
        float u0 = fmaf(p2, W_pos[2 * D + c0],     fmaf(p1, W_pos[1 * D + c0],     p0 * W_pos[0 * D + c0]));
        float u1 = fmaf(p2, W_pos[2 * D + c0 + 1], fmaf(p1, W_pos[1 * D + c0 + 1], p0 * W_pos[0 * D + c0 + 1]));
        g_agg[dst * D + c0]     = sr0 / sq0 + u0 + b_pos[c0];
        g_agg[dst * D + c0 + 1] = sr1 / sq1 + u1 + b_pos[c0 + 1];
    } else {
        g_agg[dst * D + c0]     = 0.0f;
        g_agg[dst * D + c0 + 1] = 0.0f;
    }
}

// ---------------- out projection (R8-exact): out = relu(agg @ W_out + b_out) ----------------
__global__ void k_outproj(const float* __restrict__ W_out, const float* __restrict__ b_out,
                          float* __restrict__ out) {
    __shared__ float sh[D][PAD];
    int c = threadIdx.x;
    int n0 = blockIdx.x * 16;

#pragma unroll
    for (int r = 0; r < 16; r++) sh[c][r] = g_agg[(n0 + r) * D + c];
    __syncthreads();

    float bo = b_out[c];
    unsigned long long op[8];
#pragma unroll
    for (int p = 0; p < 8; p++) op[p] = pack2(bo, bo);
#pragma unroll 4
    for (int k = 0; k < D; k++) {
        float w = W_out[k * D + c];
        unsigned long long ww = pack2(w, w);
#pragma unroll
        for (int p = 0; p < 8; p++) {
            unsigned long long ap = *(const unsigned long long*)&sh[k][2 * p];
            op[p] = fma2(ap, ww, op[p]);
        }
    }
#pragma unroll
    for (int p = 0; p < 8; p++) {
        float o0, o1;
        unpack2(op[p], o0, o1);
        out[(n0 + 2 * p) * D + c]     = fmaxf(o0, 0.0f);
        out[(n0 + 2 * p + 1) * D + c] = fmaxf(o1, 0.0f);
    }
}

// ---------------- launch ----------------
extern "C" void kernel_launch(void* const* d_in, const int* in_sizes, int n_in,
                              void* d_out, int out_size) {
    const float* x     = (const float*)d_in[0];
    const float* pos   = (const float*)d_in[1];
    const void*  ei    = d_in[2];
    const float* W_in  = (const float*)d_in[3];
    const float* b_in  = (const float*)d_in[4];
    const float* W_lin = (const float*)d_in[5];
    const float* W_src = (const float*)d_in[6];
    // d_in[7] = W_dst: dead (dst-side softmax terms cancel)
    const float* W_pos = (const float*)d_in[8];
    const float* b_pos = (const float*)d_in[9];
    const float* W_out = (const float*)d_in[10];
    const float* b_out = (const float*)d_in[11];
    float* out = (float*)d_out;

    k_nodehist<<<NPB2, 128>>>(ei, x, pos, W_in, b_in, W_lin, W_src, W_pos);
    k_scan_lookback<<<NB, 1024>>>();
    k_scatter<<<(N_EDGES / 2 + 255) / 256, 256>>>(ei);
    k_edge<<<N_NODES / 8, 256>>>(pos, W_pos, b_pos);   // captured slot #4
    k_outproj<<<N_NODES / 16, 64>>>(W_out, b_out, out);
}